// round 15
// baseline (speedup 1.0000x reference)
#include <cuda_runtime.h>

#define NN 100000
#define EE 1600000
#define BB 1024
#define SCAN_B 98   // ceil(NN/1024)
#define GEMM1_BLOCKS 1563

// ---------------- scratch (device globals; zero-initialized at load) ----------
__device__ __align__(128) float d_x12 [NN * 12];
__device__ __align__(128) float d_as  [NN * 4];
__device__ __align__(128) float d_ad  [NN * 4];
__device__ __align__(128) float d_gat [NN * 128];
__device__ __align__(128) float d_h1  [NN * 64];
__device__ __align__(128) float d_o2  [NN * 64];
__device__ __align__(128) float d_dinv[NN];
__device__ __align__(128) float d_pool[BB * 128];   // zeroed by k_head post-use
__device__ __align__(128) float d_cnt [BB];         // zeroed by k_head post-use
__device__ __align__(128) float d_fc  [BB * 64];
__device__ __align__(128) int   d_degi[NN];         // zeroed by k_head post-use
__device__ __align__(128) int   d_off [NN];
__device__ __align__(128) int   d_cur [NN];
__device__ __align__(128) int   d_csr [EE];
__device__ __align__(128) int   d_bsum [SCAN_B];
__device__             int   d_scan_ctr;            // zeroed by k_head post-use

__device__ __forceinline__ float lrelu(float x, float s) { return x < 0.f ? s * x : x; }

__device__ __forceinline__ void redAdd4(float* p, float a, float b, float c, float d) {
    asm volatile("red.global.add.v4.f32 [%0], {%1,%2,%3,%4};"
                 :: "l"(p), "f"(a), "f"(b), "f"(c), "f"(d) : "memory");
}

// ---------------- node logits + padded x + degree hist + batch counts ---------
__global__ void k_nodehist(const float* __restrict__ x, const float* __restrict__ Wg,
                           const float* __restrict__ atts, const float* __restrict__ attd,
                           const int* __restrict__ ei, const int* __restrict__ batch) {
    __shared__ float svs[36], svd[36];
    if (threadIdx.x < 36) {
        int h = threadIdx.x / 9, k = threadIdx.x % 9;
        float s = 0.f, d = 0.f;
        #pragma unroll
        for (int c = 0; c < 32; c++) {
            float w = Wg[k * 128 + h * 32 + c];
            s += w * atts[h * 32 + c];
            d += w * attd[h * 32 + c];
        }
        svs[threadIdx.x] = s;
        svd[threadIdx.x] = d;
    }
    __syncthreads();
    int idx = blockIdx.x * 256 + threadIdx.x;
    if (idx < EE) atomicAdd(&d_degi[ei[EE + idx]], 1);
    int n = idx;
    if (n >= NN) return;
    atomicAdd(&d_cnt[batch[n]], 1.0f);
    float xv[9];
    #pragma unroll
    for (int k = 0; k < 9; k++) xv[k] = x[n * 9 + k];
    #pragma unroll
    for (int k = 0; k < 9; k++) d_x12[n * 12 + k] = xv[k];
    #pragma unroll
    for (int k = 9; k < 12; k++) d_x12[n * 12 + k] = 0.f;
    #pragma unroll
    for (int h = 0; h < 4; h++) {
        float as = 0.f, ad = 0.f;
        #pragma unroll
        for (int k = 0; k < 9; k++) {
            as += xv[k] * svs[h * 9 + k];
            ad += xv[k] * svd[h * 9 + k];
        }
        d_as[n * 4 + h] = as;
        d_ad[n * 4 + h] = ad;
    }
}

// ---------------- scan + CSR fill in ONE kernel (98 all-resident blocks) ------
__global__ void k_scanfill(const int* __restrict__ ei) {
    __shared__ int sm[1024];
    __shared__ int sb[128];
    int i = blockIdx.x * 1024 + threadIdx.x;
    int v = (i < NN) ? d_degi[i] : 0;
    sm[threadIdx.x] = v;
    __syncthreads();
    for (int off = 1; off < 1024; off <<= 1) {
        int t = (threadIdx.x >= off) ? sm[threadIdx.x - off] : 0;
        __syncthreads();
        sm[threadIdx.x] += t;
        __syncthreads();
    }
    int local_excl = sm[threadIdx.x] - v;
    if (threadIdx.x == 1023) {
        d_bsum[blockIdx.x] = sm[1023];
        __threadfence();
        atomicAdd(&d_scan_ctr, 1);
    }
    // barrier 1: all block sums published (98 blocks <= 148 SMs, all resident)
    if (threadIdx.x == 0) {
        while (atomicAdd(&d_scan_ctr, 0) < SCAN_B) { }
    }
    __syncthreads();
    __threadfence();
    int t = threadIdx.x;
    if (t < 128) sb[t] = (t < SCAN_B) ? d_bsum[t] : 0;
    __syncthreads();
    for (int off = 1; off < 128; off <<= 1) {
        int tv = 0;
        if (t < 128 && t >= off) tv = sb[t - off];
        __syncthreads();
        if (t < 128) sb[t] += tv;
        __syncthreads();
    }
    int base = (blockIdx.x == 0) ? 0 : sb[blockIdx.x - 1];
    if (i < NN) {
        int o = local_excl + base;
        d_off[i] = o;
        d_cur[i] = o;
        d_dinv[i] = rsqrtf((float)(d_degi[i] + 1));
    }
    // barrier 2: all d_cur visible before edge fill
    __threadfence();
    __syncthreads();
    if (threadIdx.x == 0) {
        atomicAdd(&d_scan_ctr, 1);
        while (atomicAdd(&d_scan_ctr, 0) < 2 * SCAN_B) { }
    }
    __syncthreads();
    __threadfence();
    // CSR fill: grid-stride over edges (16 independent atomics per thread)
    for (int e = blockIdx.x * 1024 + threadIdx.x; e < EE; e += SCAN_B * 1024) {
        int dst = ei[EE + e];
        int p = atomicAdd(&d_cur[dst], 1);
        d_csr[p] = ei[e];
    }
}

// ---------------- fused GAT on hoisted x: warp/node, lane=(slot,head) ---------
__global__ void k_gat(const float* __restrict__ Wg, const float* __restrict__ bg) {
    __shared__ float sm_ax[8][4][10];
    int wb = threadIdx.x >> 5;
    int node = blockIdx.x * 8 + wb;
    if (node >= NN) return;
    int lane = threadIdx.x & 31;
    int g = lane >> 2;          // neighbor slot 0..7
    int h = lane & 3;           // head

    float add_ = d_ad[node * 4 + h];
    float m = -1e30f, s = 0.f;
    float ax[12];
    #pragma unroll
    for (int k = 0; k < 12; k++) ax[k] = 0.f;

    int start = d_off[node], cnt = d_degi[node];
    for (int p0 = 0; p0 < cnt; p0 += 8) {
        int idx = p0 + g;
        if (idx < cnt) {
            int src = d_csr[start + idx];
            float e = lrelu(d_as[src * 4 + h] + add_, 0.2f);
            float nm = fmaxf(m, e);
            float r = __expf(m - nm);
            float w = __expf(e - nm);
            s = s * r + w;
            const float4* xr = (const float4*)&d_x12[src * 12];
            float4 x0 = xr[0], x1 = xr[1], x2 = xr[2];
            ax[0] = ax[0] * r + w * x0.x;  ax[1] = ax[1] * r + w * x0.y;
            ax[2] = ax[2] * r + w * x0.z;  ax[3] = ax[3] * r + w * x0.w;
            ax[4] = ax[4] * r + w * x1.x;  ax[5] = ax[5] * r + w * x1.y;
            ax[6] = ax[6] * r + w * x1.z;  ax[7] = ax[7] * r + w * x1.w;
            ax[8] = ax[8] * r + w * x2.x;
            m = nm;
        }
    }
    #pragma unroll
    for (int off = 4; off < 32; off <<= 1) {
        float m2 = __shfl_xor_sync(0xffffffffu, m, off);
        float s2 = __shfl_xor_sync(0xffffffffu, s, off);
        float nm = fmaxf(m, m2);
        float r1 = __expf(m - nm);
        float r2 = __expf(m2 - nm);
        s = s * r1 + s2 * r2;
        #pragma unroll
        for (int k = 0; k < 9; k++) {
            float a2 = __shfl_xor_sync(0xffffffffu, ax[k], off);
            ax[k] = ax[k] * r1 + a2 * r2;
        }
        m = nm;
    }
    if (lane < 4) {
        float es = lrelu(d_as[node * 4 + lane] + add_, 0.2f);
        float nm = fmaxf(m, es);
        float r = __expf(m - nm);
        float wse = __expf(es - nm);
        float st = s * r + wse;
        float inv = 1.f / (st + 1e-16f);
        #pragma unroll
        for (int k = 0; k < 9; k++)
            sm_ax[wb][lane][k] = (ax[k] * r + wse * d_x12[node * 12 + k]) * inv;
    }
    __syncwarp();
    int hh = lane >> 3;
    float a[9];
    #pragma unroll
    for (int k = 0; k < 9; k++) a[k] = sm_ax[wb][hh][k];
    float4 o = *(const float4*)&bg[lane * 4];
    #pragma unroll
    for (int k = 0; k < 9; k++) {
        float4 wr = *(const float4*)&Wg[k * 128 + lane * 4];
        o.x += a[k] * wr.x; o.y += a[k] * wr.y;
        o.z += a[k] * wr.z; o.w += a[k] * wr.w;
    }
    o.x = lrelu(o.x, 0.01f); o.y = lrelu(o.y, 0.01f);
    o.z = lrelu(o.z, 0.01f); o.w = lrelu(o.w, 0.01f);
    *(float4*)&d_gat[node * 128 + lane * 4] = o;
}

// ---------------- GEMM1 + fused sequence branch (block-range split) -----------
__global__ void k_gemm1seq(const float* __restrict__ W2,
                           const float* __restrict__ seq,
                           const float* __restrict__ c1w, const float* __restrict__ c1b,
                           const float* __restrict__ bn1g, const float* __restrict__ bn1b,
                           const float* __restrict__ bn1m, const float* __restrict__ bn1v,
                           const float* __restrict__ c2w, const float* __restrict__ c2b,
                           const float* __restrict__ bn2g, const float* __restrict__ bn2b,
                           const float* __restrict__ bn2m, const float* __restrict__ bn2v,
                           const float* __restrict__ fcW, const float* __restrict__ fcb) {
    __shared__ float sbuf[8192];                   // 32 KB shared by both paths
    int tid = threadIdx.x;                         // 256 threads
    if (blockIdx.x < GEMM1_BLOCKS) {
        float* Ws = sbuf;                          // [128][64]
        for (int i = tid; i < 128 * 64; i += 256) Ws[i] = W2[i];
        __syncthreads();
        int q = tid & 15;
        int nl = tid >> 4;
        for (int n0 = blockIdx.x * 64; n0 < NN; n0 += GEMM1_BLOCKS * 64) {
            int nb = n0 + nl * 4;
            int m0 = min(nb + 0, NN - 1), m1 = min(nb + 1, NN - 1);
            int m2 = min(nb + 2, NN - 1), m3 = min(nb + 3, NN - 1);
            const float4* gA = (const float4*)&d_gat[m0 * 128];
            const float4* gB = (const float4*)&d_gat[m1 * 128];
            const float4* gC = (const float4*)&d_gat[m2 * 128];
            const float4* gD = (const float4*)&d_gat[m3 * 128];
            float4 aA = make_float4(0.f,0.f,0.f,0.f), aB = aA, aC = aA, aD = aA;
            #pragma unroll
            for (int kk = 0; kk < 32; kk++) {
                float4 w0 = *(const float4*)&Ws[(kk * 4 + 0) * 64 + q * 4];
                float4 w1 = *(const float4*)&Ws[(kk * 4 + 1) * 64 + q * 4];
                float4 w2 = *(const float4*)&Ws[(kk * 4 + 2) * 64 + q * 4];
                float4 w3 = *(const float4*)&Ws[(kk * 4 + 3) * 64 + q * 4];
                float4 v;
                v = gA[kk];
                aA.x += v.x*w0.x + v.y*w1.x + v.z*w2.x + v.w*w3.x;
                aA.y += v.x*w0.y + v.y*w1.y + v.z*w2.y + v.w*w3.y;
                aA.z += v.x*w0.z + v.y*w1.z + v.z*w2.z + v.w*w3.z;
                aA.w += v.x*w0.w + v.y*w1.w + v.z*w2.w + v.w*w3.w;
                v = gB[kk];
                aB.x += v.x*w0.x + v.y*w1.x + v.z*w2.x + v.w*w3.x;
                aB.y += v.x*w0.y + v.y*w1.y + v.z*w2.y + v.w*w3.y;
                aB.z += v.x*w0.z + v.y*w1.z + v.z*w2.z + v.w*w3.z;
                aB.w += v.x*w0.w + v.y*w1.w + v.z*w2.w + v.w*w3.w;
                v = gC[kk];
                aC.x += v.x*w0.x + v.y*w1.x + v.z*w2.x + v.w*w3.x;
                aC.y += v.x*w0.y + v.y*w1.y + v.z*w2.y + v.w*w3.y;
                aC.z += v.x*w0.z + v.y*w1.z + v.z*w2.z + v.w*w3.z;
                aC.w += v.x*w0.w + v.y*w1.w + v.z*w2.w + v.w*w3.w;
                v = gD[kk];
                aD.x += v.x*w0.x + v.y*w1.x + v.z*w2.x + v.w*w3.x;
                aD.y += v.x*w0.y + v.y*w1.y + v.z*w2.y + v.w*w3.y;
                aD.z += v.x*w0.z + v.y*w1.z + v.z*w2.z + v.w*w3.z;
                aD.w += v.x*w0.w + v.y*w1.w + v.z*w2.w + v.w*w3.w;
            }
            if (nb + 0 < NN) *(float4*)&d_h1[(nb + 0) * 64 + q * 4] = aA;
            if (nb + 1 < NN) *(float4*)&d_h1[(nb + 1) * 64 + q * 4] = aB;
            if (nb + 2 < NN) *(float4*)&d_h1[(nb + 2) * 64 + q * 4] = aC;
            if (nb + 3 < NN) *(float4*)&d_h1[(nb + 3) * 64 + q * 4] = aD;
        }
    } else {
        int b = blockIdx.x - GEMM1_BLOCKS;         // 0..BB-1
        float* sseq = sbuf;                        // [600]
        float* s1   = sbuf + 600;                  // [1152]
        float* s2   = sbuf + 600 + 1152;           // [1024]
        float* part = sbuf + 600 + 1152 + 1024;    // [4*64]
        for (int i = tid; i < 600; i += 256) sseq[i] = seq[b * 600 + i];
        __syncthreads();
        for (int r = tid; r < 1152; r += 256) {
            int co = r / 18, t = r % 18;
            float acc = c1b[co];
            #pragma unroll 5
            for (int ci = 0; ci < 30; ci++) {
                const float* sp = &sseq[ci * 20 + t];
                const float* wp = &c1w[(co * 30 + ci) * 3];
                acc += sp[0] * wp[0] + sp[1] * wp[1] + sp[2] * wp[2];
            }
            acc = (acc - bn1m[co]) * rsqrtf(bn1v[co] + 1e-5f) * bn1g[co] + bn1b[co];
            s1[r] = lrelu(acc, 0.01f);
        }
        __syncthreads();
        for (int r = tid; r < 1024; r += 256) {
            int co = r >> 4, t = r & 15;
            float acc = c2b[co];
            #pragma unroll 8
            for (int ci = 0; ci < 64; ci++) {
                const float* sp = &s1[ci * 18 + t];
                const float* wp = &c2w[(co * 64 + ci) * 3];
                acc += sp[0] * wp[0] + sp[1] * wp[1] + sp[2] * wp[2];
            }
            acc = (acc - bn2m[co]) * rsqrtf(bn2v[co] + 1e-5f) * bn2g[co] + bn2b[co];
            s2[r] = lrelu(acc, 0.01f);
        }
        __syncthreads();
        {
            int o = tid & 63, qq = tid >> 6;
            float acc = 0.f;
            int k0 = qq * 256;
            #pragma unroll 8
            for (int k = 0; k < 256; k++)
                acc += s2[k0 + k] * fcW[(k0 + k) * 64 + o];
            part[qq * 64 + o] = acc;
        }
        __syncthreads();
        if (tid < 64)
            d_fc[b * 64 + tid] = fcb[tid] + part[0 * 64 + tid] + part[1 * 64 + tid]
                                          + part[2 * 64 + tid] + part[3 * 64 + tid];
    }
}

// ---------------- GCN1 gather (warp per node) ----------------------------------
__global__ void k_gcn1(const float* __restrict__ b2) {
    int gw = (blockIdx.x * 256 + threadIdx.x) >> 5;
    if (gw >= NN) return;
    int lane = threadIdx.x & 31;
    int d = gw;
    float did = d_dinv[d];

    float2 hv = *(const float2*)&d_h1[d * 64 + lane * 2];
    float2 acc; acc.x = hv.x * did; acc.y = hv.y * did;

    int start = d_off[d];
    int cntE  = d_degi[d];
    for (int p0 = 0; p0 < cntE; p0 += 32) {
        int   src_l = 0;
        float dv_l  = 0.f;
        if (p0 + lane < cntE) { src_l = d_csr[start + p0 + lane]; dv_l = d_dinv[src_l]; }
        int lim = min(32, cntE - p0);
        for (int j = 0; j < lim; j++) {
            int   src = __shfl_sync(0xffffffffu, src_l, j);
            float dv  = __shfl_sync(0xffffffffu, dv_l, j);
            float2 v = *(const float2*)&d_h1[src * 64 + lane * 2];
            acc.x += v.x * dv; acc.y += v.y * dv;
        }
    }
    float2 o;
    o.x = lrelu(acc.x * did + b2[lane * 2 + 0], 0.01f);
    o.y = lrelu(acc.y * did + b2[lane * 2 + 1], 0.01f);
    *(float2*)&d_o2[d * 64 + lane * 2] = o;
}

// ---------------- fused GCN2 gather + GEMM2 + bias + lrelu + pool -------------
__global__ void k_gcn2gemm(const float* __restrict__ W3, const float* __restrict__ b3,
                           const int* __restrict__ batch) {
    __shared__ float Ws[64 * 128];                 // 32 KB [k][o]
    __shared__ float sAg[8][64];                   // 2 KB aggregated rows
    int tid = threadIdx.x;                         // 256 threads = 8 warps
    for (int i = tid; i < 64 * 128; i += 256) Ws[i] = W3[i];
    __syncthreads();
    int w = tid >> 5, lane = tid & 31;
    int q = tid & 31, nl = tid >> 5;
    float4 bb = *(const float4*)&b3[q * 4];
    for (int n0 = blockIdx.x * 8; n0 < NN; n0 += gridDim.x * 8) {
        // ---- phase 1: each warp aggregates one node's o2 row (gcn2agg body) ----
        int d = n0 + w;                            // NN % 8 == 0 -> always valid
        float did = d_dinv[d];
        float2 hv = *(const float2*)&d_o2[d * 64 + lane * 2];
        float2 acc; acc.x = hv.x * did; acc.y = hv.y * did;
        int start = d_off[d];
        int cntE  = d_degi[d];
        for (int p0 = 0; p0 < cntE; p0 += 32) {
            int   src_l = 0;
            float dv_l  = 0.f;
            if (p0 + lane < cntE) { src_l = d_csr[start + p0 + lane]; dv_l = d_dinv[src_l]; }
            int lim = min(32, cntE - p0);
            for (int j = 0; j < lim; j++) {
                int   src = __shfl_sync(0xffffffffu, src_l, j);
                float dv  = __shfl_sync(0xffffffffu, dv_l, j);
                float2 v = *(const float2*)&d_o2[src * 64 + lane * 2];
                acc.x += v.x * dv; acc.y += v.y * dv;
            }
        }
        sAg[w][lane * 2 + 0] = acc.x * did;
        sAg[w][lane * 2 + 1] = acc.y * did;
        __syncthreads();
        // ---- phase 2: GEMM the 8 rows against smem W3, fused epilogue ----------
        const float4* g4 = (const float4*)&sAg[nl][0];
        float4 aO = bb;
        #pragma unroll
        for (int kk = 0; kk < 16; kk++) {
            float4 v = g4[kk];
            float4 w0 = *(const float4*)&Ws[(kk * 4 + 0) * 128 + q * 4];
            float4 w1 = *(const float4*)&Ws[(kk * 4 + 1) * 128 + q * 4];
            float4 w2 = *(const float4*)&Ws[(kk * 4 + 2) * 128 + q * 4];
            float4 w3 = *(const float4*)&Ws[(kk * 4 + 3) * 128 + q * 4];
            aO.x += v.x*w0.x + v.y*w1.x + v.z*w2.x + v.w*w3.x;
            aO.y += v.x*w0.y + v.y*w1.y + v.z*w2.y + v.w*w3.y;
            aO.z += v.x*w0.z + v.y*w1.z + v.z*w2.z + v.w*w3.z;
            aO.w += v.x*w0.w + v.y*w1.w + v.z*w2.w + v.w*w3.w;
        }
        int bDst = batch[n0 + nl];
        redAdd4(&d_pool[bDst * 128 + q * 4],
                lrelu(aO.x,0.01f), lrelu(aO.y,0.01f), lrelu(aO.z,0.01f), lrelu(aO.w,0.01f));
        __syncthreads();                           // before sAg overwrite
    }
}

// ---------------- fusion + classifier head + state reset ----------------------
__global__ void k_head(const float* __restrict__ fusW, const float* __restrict__ fusb,
                       const float* __restrict__ c1W, const float* __restrict__ c1b,
                       const float* __restrict__ c3W, const float* __restrict__ c3b,
                       float* __restrict__ out) {
    __shared__ float comb[192], t1[128], t2[64];
    int b = blockIdx.x, tid = threadIdx.x;          // 128 threads
    if (tid < 128) comb[tid] = d_pool[b * 128 + tid] / fmaxf(d_cnt[b], 1.0f);
    if (tid < 64)  comb[128 + tid] = d_fc[b * 64 + tid];
    __syncthreads();
    // ---- reset persistent state for the next graph replay (post-read) ----
    d_pool[b * 128 + tid] = 0.f;
    if (tid == 0) d_cnt[b] = 0.f;
    if (b == 0 && tid == 0) d_scan_ctr = 0;
    {
        int gi = b * 128 + tid;                     // BB*128 = 131072 >= NN
        if (gi < NN) d_degi[gi] = 0;
    }
    // ----------------------------------------------------------------------
    float acc = fusb[tid];
    #pragma unroll 8
    for (int k = 0; k < 192; k++) acc += comb[k] * fusW[k * 128 + tid];
    t1[tid] = lrelu(acc, 0.01f);
    __syncthreads();
    if (tid < 64) {
        float a = c1b[tid];
        #pragma unroll 8
        for (int k = 0; k < 128; k++) a += t1[k] * c1W[k * 64 + tid];
        t2[tid] = lrelu(a, 0.01f);
    }
    __syncthreads();
    if (tid == 0) {
        float a = c3b[0];
        #pragma unroll 8
        for (int k = 0; k < 64; k++) a += t2[k] * c3W[k];
        out[b] = a;
    }
}

// ---------------- launch ------------------------------------------------------
extern "C" void kernel_launch(void* const* d_in, const int* in_sizes, int n_in,
                              void* d_out, int out_size) {
    const float* x     = (const float*)d_in[0];
    const int*   ei    = (const int*)  d_in[1];
    const int*   batch = (const int*)  d_in[2];
    const float* seq   = (const float*)d_in[3];
    const float* Wg    = (const float*)d_in[4];
    const float* atts  = (const float*)d_in[5];
    const float* attd  = (const float*)d_in[6];
    const float* bg    = (const float*)d_in[7];
    const float* W2    = (const float*)d_in[8];
    const float* b2    = (const float*)d_in[9];
    const float* W3    = (const float*)d_in[10];
    const float* b3    = (const float*)d_in[11];
    const float* c1w   = (const float*)d_in[12];
    const float* c1bv  = (const float*)d_in[13];
    const float* c2w   = (const float*)d_in[14];
    const float* c2bv  = (const float*)d_in[15];
    const float* bn1g  = (const float*)d_in[16];
    const float* bn1b  = (const float*)d_in[17];
    const float* bn1m  = (const float*)d_in[18];
    const float* bn1v  = (const float*)d_in[19];
    const float* bn2g  = (const float*)d_in[20];
    const float* bn2b  = (const float*)d_in[21];
    const float* bn2m  = (const float*)d_in[22];
    const float* bn2v  = (const float*)d_in[23];
    const float* fcW   = (const float*)d_in[24];
    const float* fcb   = (const float*)d_in[25];
    const float* fusW  = (const float*)d_in[26];
    const float* fusb  = (const float*)d_in[27];
    const float* cls1W = (const float*)d_in[28];
    const float* cls1b = (const float*)d_in[29];
    const float* cls3W = (const float*)d_in[30];
    const float* cls3b = (const float*)d_in[31];
    float* out = (float*)d_out;

    k_nodehist <<<(EE + 255) / 256, 256>>>(x, Wg, atts, attd, ei, batch);
    k_scanfill <<<SCAN_B, 1024>>>(ei);
    k_gat      <<<12500, 256>>>(Wg, bg);
    k_gemm1seq <<<GEMM1_BLOCKS + BB, 256>>>(W2, seq, c1w, c1bv, bn1g, bn1b, bn1m, bn1v,
                                            c2w, c2bv, bn2g, bn2b, bn2m, bn2v, fcW, fcb);
    k_gcn1     <<<12500, 256>>>(b2);
    k_gcn2gemm <<<1563, 256>>>(W3, b3, batch);
    k_head     <<<BB, 128>>>(fusW, fusb, cls1W, cls1b, cls3W, cls3b, out);
}

// round 16
// speedup vs baseline: 1.1855x; 1.1855x over previous
#include <cuda_runtime.h>

#define NN 100000
#define EE 1600000
#define BB 1024
#define SCAN_B 98   // ceil(NN/1024)
#define GEMM1_BLOCKS 1563

// ---------------- scratch (device globals; zero-initialized at load) ----------
__device__ __align__(128) float d_x12 [NN * 12];
__device__ __align__(128) float d_as  [NN * 4];
__device__ __align__(128) float d_ad  [NN * 4];
__device__ __align__(128) float d_gat [NN * 128];
__device__ __align__(128) float d_h1  [NN * 64];
__device__ __align__(128) float d_o2  [NN * 64];
__device__ __align__(128) float d_ag2 [NN * 64];
__device__ __align__(128) float d_dinv[NN];
__device__ __align__(128) float d_pool[BB * 128];   // zeroed by k_head post-use
__device__ __align__(128) float d_cnt [BB];         // zeroed by k_head post-use
__device__ __align__(128) float d_fc  [BB * 64];
__device__ __align__(128) int   d_degi[NN];         // zeroed by k_head post-use
__device__ __align__(128) int   d_off [NN];
__device__ __align__(128) int   d_cur [NN];
__device__ __align__(128) int   d_csr [EE];
__device__ __align__(128) int   d_bsum [SCAN_B];
__device__             int   d_scan_ctr;            // zeroed by k_head post-use

__device__ __forceinline__ float lrelu(float x, float s) { return x < 0.f ? s * x : x; }

__device__ __forceinline__ void redAdd4(float* p, float a, float b, float c, float d) {
    asm volatile("red.global.add.v4.f32 [%0], {%1,%2,%3,%4};"
                 :: "l"(p), "f"(a), "f"(b), "f"(c), "f"(d) : "memory");
}

// ---------------- node logits + padded x + degree hist + batch counts ---------
__global__ void k_nodehist(const float* __restrict__ x, const float* __restrict__ Wg,
                           const float* __restrict__ atts, const float* __restrict__ attd,
                           const int* __restrict__ ei, const int* __restrict__ batch) {
    __shared__ float svs[36], svd[36];
    if (threadIdx.x < 36) {
        int h = threadIdx.x / 9, k = threadIdx.x % 9;
        float s = 0.f, d = 0.f;
        #pragma unroll
        for (int c = 0; c < 32; c++) {
            float w = Wg[k * 128 + h * 32 + c];
            s += w * atts[h * 32 + c];
            d += w * attd[h * 32 + c];
        }
        svs[threadIdx.x] = s;
        svd[threadIdx.x] = d;
    }
    __syncthreads();
    int idx = blockIdx.x * 256 + threadIdx.x;
    if (idx < EE) atomicAdd(&d_degi[ei[EE + idx]], 1);
    int n = idx;
    if (n >= NN) return;
    atomicAdd(&d_cnt[batch[n]], 1.0f);
    float xv[9];
    #pragma unroll
    for (int k = 0; k < 9; k++) xv[k] = x[n * 9 + k];
    #pragma unroll
    for (int k = 0; k < 9; k++) d_x12[n * 12 + k] = xv[k];
    #pragma unroll
    for (int k = 9; k < 12; k++) d_x12[n * 12 + k] = 0.f;
    #pragma unroll
    for (int h = 0; h < 4; h++) {
        float as = 0.f, ad = 0.f;
        #pragma unroll
        for (int k = 0; k < 9; k++) {
            as += xv[k] * svs[h * 9 + k];
            ad += xv[k] * svd[h * 9 + k];
        }
        d_as[n * 4 + h] = as;
        d_ad[n * 4 + h] = ad;
    }
}

// ---------------- single-kernel exclusive scan (98 blocks, all-resident) ------
__global__ void k_scan() {
    __shared__ int sm[1024];
    __shared__ int sb[128];
    int i = blockIdx.x * 1024 + threadIdx.x;
    int v = (i < NN) ? d_degi[i] : 0;
    sm[threadIdx.x] = v;
    __syncthreads();
    for (int off = 1; off < 1024; off <<= 1) {
        int t = (threadIdx.x >= off) ? sm[threadIdx.x - off] : 0;
        __syncthreads();
        sm[threadIdx.x] += t;
        __syncthreads();
    }
    int local_excl = sm[threadIdx.x] - v;
    if (threadIdx.x == 1023) {
        d_bsum[blockIdx.x] = sm[1023];
        __threadfence();
        atomicAdd(&d_scan_ctr, 1);
    }
    if (threadIdx.x == 0) {
        while (atomicAdd(&d_scan_ctr, 0) < SCAN_B) { }
    }
    __syncthreads();
    __threadfence();
    int t = threadIdx.x;
    if (t < 128) sb[t] = (t < SCAN_B) ? d_bsum[t] : 0;
    __syncthreads();
    for (int off = 1; off < 128; off <<= 1) {
        int tv = 0;
        if (t < 128 && t >= off) tv = sb[t - off];
        __syncthreads();
        if (t < 128) sb[t] += tv;
        __syncthreads();
    }
    int base = (blockIdx.x == 0) ? 0 : sb[blockIdx.x - 1];
    if (i < NN) {
        int o = local_excl + base;
        d_off[i] = o;
        d_cur[i] = o;
        d_dinv[i] = rsqrtf((float)(d_degi[i] + 1));
    }
}

// ---------------- CSR fill ------------------------------------------------------
__global__ void k_fill(const int* __restrict__ ei) {
    int idx = blockIdx.x * 256 + threadIdx.x;
    if (idx < EE) {
        int dst = ei[EE + idx];
        int p = atomicAdd(&d_cur[dst], 1);
        d_csr[p] = ei[idx];
    }
}

// ---------------- fused GAT on hoisted x: warp/node, lane=(slot,head) ---------
__global__ void k_gat(const float* __restrict__ Wg, const float* __restrict__ bg) {
    __shared__ float sm_ax[8][4][10];
    int wb = threadIdx.x >> 5;
    int node = blockIdx.x * 8 + wb;
    if (node >= NN) return;
    int lane = threadIdx.x & 31;
    int g = lane >> 2;          // neighbor slot 0..7
    int h = lane & 3;           // head

    float add_ = d_ad[node * 4 + h];
    float m = -1e30f, s = 0.f;
    float ax[12];
    #pragma unroll
    for (int k = 0; k < 12; k++) ax[k] = 0.f;

    int start = d_off[node], cnt = d_degi[node];
    for (int p0 = 0; p0 < cnt; p0 += 8) {
        int idx = p0 + g;
        if (idx < cnt) {
            int src = d_csr[start + idx];
            float e = lrelu(d_as[src * 4 + h] + add_, 0.2f);
            float nm = fmaxf(m, e);
            float r = __expf(m - nm);
            float w = __expf(e - nm);
            s = s * r + w;
            const float4* xr = (const float4*)&d_x12[src * 12];
            float4 x0 = xr[0], x1 = xr[1], x2 = xr[2];
            ax[0] = ax[0] * r + w * x0.x;  ax[1] = ax[1] * r + w * x0.y;
            ax[2] = ax[2] * r + w * x0.z;  ax[3] = ax[3] * r + w * x0.w;
            ax[4] = ax[4] * r + w * x1.x;  ax[5] = ax[5] * r + w * x1.y;
            ax[6] = ax[6] * r + w * x1.z;  ax[7] = ax[7] * r + w * x1.w;
            ax[8] = ax[8] * r + w * x2.x;
            m = nm;
        }
    }
    #pragma unroll
    for (int off = 4; off < 32; off <<= 1) {
        float m2 = __shfl_xor_sync(0xffffffffu, m, off);
        float s2 = __shfl_xor_sync(0xffffffffu, s, off);
        float nm = fmaxf(m, m2);
        float r1 = __expf(m - nm);
        float r2 = __expf(m2 - nm);
        s = s * r1 + s2 * r2;
        #pragma unroll
        for (int k = 0; k < 9; k++) {
            float a2 = __shfl_xor_sync(0xffffffffu, ax[k], off);
            ax[k] = ax[k] * r1 + a2 * r2;
        }
        m = nm;
    }
    if (lane < 4) {
        float es = lrelu(d_as[node * 4 + lane] + add_, 0.2f);
        float nm = fmaxf(m, es);
        float r = __expf(m - nm);
        float wse = __expf(es - nm);
        float st = s * r + wse;
        float inv = 1.f / (st + 1e-16f);
        #pragma unroll
        for (int k = 0; k < 9; k++)
            sm_ax[wb][lane][k] = (ax[k] * r + wse * d_x12[node * 12 + k]) * inv;
    }
    __syncwarp();
    int hh = lane >> 3;
    float a[9];
    #pragma unroll
    for (int k = 0; k < 9; k++) a[k] = sm_ax[wb][hh][k];
    float4 o = *(const float4*)&bg[lane * 4];
    #pragma unroll
    for (int k = 0; k < 9; k++) {
        float4 wr = *(const float4*)&Wg[k * 128 + lane * 4];
        o.x += a[k] * wr.x; o.y += a[k] * wr.y;
        o.z += a[k] * wr.z; o.w += a[k] * wr.w;
    }
    o.x = lrelu(o.x, 0.01f); o.y = lrelu(o.y, 0.01f);
    o.z = lrelu(o.z, 0.01f); o.w = lrelu(o.w, 0.01f);
    *(float4*)&d_gat[node * 128 + lane * 4] = o;
}

// ---------------- GEMM1 + fused sequence branch (block-range split) -----------
// Seq path stages conv weights in smem (kills the scattered-LDG L1 storm).
__global__ void k_gemm1seq(const float* __restrict__ W2,
                           const float* __restrict__ seq,
                           const float* __restrict__ c1w, const float* __restrict__ c1b,
                           const float* __restrict__ bn1g, const float* __restrict__ bn1b,
                           const float* __restrict__ bn1m, const float* __restrict__ bn1v,
                           const float* __restrict__ c2w, const float* __restrict__ c2b,
                           const float* __restrict__ bn2g, const float* __restrict__ bn2b,
                           const float* __restrict__ bn2m, const float* __restrict__ bn2v,
                           const float* __restrict__ fcW, const float* __restrict__ fcb) {
    __shared__ float sbuf[15360];                  // 61.4 KB union
    int tid = threadIdx.x;                         // 256 threads
    if (blockIdx.x < GEMM1_BLOCKS) {
        // ---------------- GEMM1 path: h1 = d_gat @ W2, 4 nodes/thread ----------
        float* Ws = sbuf;                          // [128][64] = 32 KB
        for (int i = tid; i < 128 * 64; i += 256) Ws[i] = W2[i];
        __syncthreads();
        int q = tid & 15;
        int nl = tid >> 4;
        for (int n0 = blockIdx.x * 64; n0 < NN; n0 += GEMM1_BLOCKS * 64) {
            int nb = n0 + nl * 4;
            int m0 = min(nb + 0, NN - 1), m1 = min(nb + 1, NN - 1);
            int m2 = min(nb + 2, NN - 1), m3 = min(nb + 3, NN - 1);
            const float4* gA = (const float4*)&d_gat[m0 * 128];
            const float4* gB = (const float4*)&d_gat[m1 * 128];
            const float4* gC = (const float4*)&d_gat[m2 * 128];
            const float4* gD = (const float4*)&d_gat[m3 * 128];
            float4 aA = make_float4(0.f,0.f,0.f,0.f), aB = aA, aC = aA, aD = aA;
            #pragma unroll
            for (int kk = 0; kk < 32; kk++) {
                float4 w0 = *(const float4*)&Ws[(kk * 4 + 0) * 64 + q * 4];
                float4 w1 = *(const float4*)&Ws[(kk * 4 + 1) * 64 + q * 4];
                float4 w2 = *(const float4*)&Ws[(kk * 4 + 2) * 64 + q * 4];
                float4 w3 = *(const float4*)&Ws[(kk * 4 + 3) * 64 + q * 4];
                float4 v;
                v = gA[kk];
                aA.x += v.x*w0.x + v.y*w1.x + v.z*w2.x + v.w*w3.x;
                aA.y += v.x*w0.y + v.y*w1.y + v.z*w2.y + v.w*w3.y;
                aA.z += v.x*w0.z + v.y*w1.z + v.z*w2.z + v.w*w3.z;
                aA.w += v.x*w0.w + v.y*w1.w + v.z*w2.w + v.w*w3.w;
                v = gB[kk];
                aB.x += v.x*w0.x + v.y*w1.x + v.z*w2.x + v.w*w3.x;
                aB.y += v.x*w0.y + v.y*w1.y + v.z*w2.y + v.w*w3.y;
                aB.z += v.x*w0.z + v.y*w1.z + v.z*w2.z + v.w*w3.z;
                aB.w += v.x*w0.w + v.y*w1.w + v.z*w2.w + v.w*w3.w;
                v = gC[kk];
                aC.x += v.x*w0.x + v.y*w1.x + v.z*w2.x + v.w*w3.x;
                aC.y += v.x*w0.y + v.y*w1.y + v.z*w2.y + v.w*w3.y;
                aC.z += v.x*w0.z + v.y*w1.z + v.z*w2.z + v.w*w3.z;
                aC.w += v.x*w0.w + v.y*w1.w + v.z*w2.w + v.w*w3.w;
                v = gD[kk];
                aD.x += v.x*w0.x + v.y*w1.x + v.z*w2.x + v.w*w3.x;
                aD.y += v.x*w0.y + v.y*w1.y + v.z*w2.y + v.w*w3.y;
                aD.z += v.x*w0.z + v.y*w1.z + v.z*w2.z + v.w*w3.z;
                aD.w += v.x*w0.w + v.y*w1.w + v.z*w2.w + v.w*w3.w;
            }
            if (nb + 0 < NN) *(float4*)&d_h1[(nb + 0) * 64 + q * 4] = aA;
            if (nb + 1 < NN) *(float4*)&d_h1[(nb + 1) * 64 + q * 4] = aB;
            if (nb + 2 < NN) *(float4*)&d_h1[(nb + 2) * 64 + q * 4] = aC;
            if (nb + 3 < NN) *(float4*)&d_h1[(nb + 3) * 64 + q * 4] = aD;
        }
    } else {
        // ---------------- sequence path: smem-staged weights -------------------
        int b = blockIdx.x - GEMM1_BLOCKS;         // 0..BB-1
        float* sw   = sbuf;                        // weights region [12288]
        float* sseq = sbuf + 12288;                // [600]
        float* s1   = sbuf + 12888;                // [1152]
        float* s2   = sbuf + 14040;                // [1024]
        float* part = sbuf + 15064;                // [256]
        for (int i = tid; i < 600; i += 256) sseq[i] = seq[b * 600 + i];
        for (int i = tid; i < 5760; i += 256) sw[i] = c1w[i];       // 64*30*3
        __syncthreads();
        // stage 1: conv1 + BN + lrelu -> s1[64][18]
        for (int r = tid; r < 1152; r += 256) {
            int co = r / 18, t = r % 18;
            float acc = c1b[co];
            #pragma unroll 5
            for (int ci = 0; ci < 30; ci++) {
                const float* sp = &sseq[ci * 20 + t];
                const float* wp = &sw[(co * 30 + ci) * 3];
                acc += sp[0] * wp[0] + sp[1] * wp[1] + sp[2] * wp[2];
            }
            acc = (acc - bn1m[co]) * rsqrtf(bn1v[co] + 1e-5f) * bn1g[co] + bn1b[co];
            s1[r] = lrelu(acc, 0.01f);
        }
        __syncthreads();
        for (int i = tid; i < 12288; i += 256) sw[i] = c2w[i];      // 64*64*3
        __syncthreads();
        // stage 2: conv2 + BN + lrelu -> s2[64][16]
        for (int r = tid; r < 1024; r += 256) {
            int co = r >> 4, t = r & 15;
            float acc = c2b[co];
            #pragma unroll 8
            for (int ci = 0; ci < 64; ci++) {
                const float* sp = &s1[ci * 18 + t];
                const float* wp = &sw[(co * 64 + ci) * 3];
                acc += sp[0] * wp[0] + sp[1] * wp[1] + sp[2] * wp[2];
            }
            acc = (acc - bn2m[co]) * rsqrtf(bn2v[co] + 1e-5f) * bn2g[co] + bn2b[co];
            s2[r] = lrelu(acc, 0.01f);
        }
        __syncthreads();
        // stage 3: fc 1024 -> 64
        {
            int o = tid & 63, qq = tid >> 6;
            float acc = 0.f;
            int k0 = qq * 256;
            #pragma unroll 8
            for (int k = 0; k < 256; k++)
                acc += s2[k0 + k] * fcW[(k0 + k) * 64 + o];
            part[qq * 64 + o] = acc;
        }
        __syncthreads();
        if (tid < 64)
            d_fc[b * 64 + tid] = fcb[tid] + part[0 * 64 + tid] + part[1 * 64 + tid]
                                          + part[2 * 64 + tid] + part[3 * 64 + tid];
    }
}

// ---------------- GCN1 gather (warp per node) ----------------------------------
__global__ void k_gcn1(const float* __restrict__ b2) {
    int gw = (blockIdx.x * 256 + threadIdx.x) >> 5;
    if (gw >= NN) return;
    int lane = threadIdx.x & 31;
    int d = gw;
    float did = d_dinv[d];

    float2 hv = *(const float2*)&d_h1[d * 64 + lane * 2];
    float2 acc; acc.x = hv.x * did; acc.y = hv.y * did;

    int start = d_off[d];
    int cntE  = d_degi[d];
    for (int p0 = 0; p0 < cntE; p0 += 32) {
        int   src_l = 0;
        float dv_l  = 0.f;
        if (p0 + lane < cntE) { src_l = d_csr[start + p0 + lane]; dv_l = d_dinv[src_l]; }
        int lim = min(32, cntE - p0);
        for (int j = 0; j < lim; j++) {
            int   src = __shfl_sync(0xffffffffu, src_l, j);
            float dv  = __shfl_sync(0xffffffffu, dv_l, j);
            float2 v = *(const float2*)&d_h1[src * 64 + lane * 2];
            acc.x += v.x * dv; acc.y += v.y * dv;
        }
    }
    float2 o;
    o.x = lrelu(acc.x * did + b2[lane * 2 + 0], 0.01f);
    o.y = lrelu(acc.y * did + b2[lane * 2 + 1], 0.01f);
    *(float2*)&d_o2[d * 64 + lane * 2] = o;
}

// ---------------- GCN2 aggregation on o2 --------------------------------------
__global__ void k_gcn2agg() {
    int gw = (blockIdx.x * 256 + threadIdx.x) >> 5;
    if (gw >= NN) return;
    int lane = threadIdx.x & 31;
    int d = gw;
    float did = d_dinv[d];

    float2 hv = *(const float2*)&d_o2[d * 64 + lane * 2];
    float2 acc; acc.x = hv.x * did; acc.y = hv.y * did;

    int start = d_off[d];
    int cntE  = d_degi[d];
    for (int p0 = 0; p0 < cntE; p0 += 32) {
        int   src_l = 0;
        float dv_l  = 0.f;
        if (p0 + lane < cntE) { src_l = d_csr[start + p0 + lane]; dv_l = d_dinv[src_l]; }
        int lim = min(32, cntE - p0);
        for (int j = 0; j < lim; j++) {
            int   src = __shfl_sync(0xffffffffu, src_l, j);
            float dv  = __shfl_sync(0xffffffffu, dv_l, j);
            float2 v = *(const float2*)&d_o2[src * 64 + lane * 2];
            acc.x += v.x * dv; acc.y += v.y * dv;
        }
    }
    float2 o;
    o.x = acc.x * did;
    o.y = acc.y * did;
    *(float2*)&d_ag2[d * 64 + lane * 2] = o;
}

// ---------------- GEMM2 + bias + lrelu + pool, 4 nodes/thread -----------------
__global__ void k_gemm2pool(const float* __restrict__ W3, const float* __restrict__ b3,
                            const int* __restrict__ batch) {
    __shared__ float Ws[64 * 128];                 // [k][o]
    for (int i = threadIdx.x; i < 64 * 128; i += 256) Ws[i] = W3[i];
    __syncthreads();
    int q = threadIdx.x & 31;
    int nl = threadIdx.x >> 5;
    float4 bb = *(const float4*)&b3[q * 4];
    for (int n0 = blockIdx.x * 32; n0 < NN; n0 += gridDim.x * 32) {
        int nb = n0 + nl * 4;                      // NN % 32 == 0 -> no tail
        const float4* gA = (const float4*)&d_ag2[(nb + 0) * 64];
        const float4* gB = (const float4*)&d_ag2[(nb + 1) * 64];
        const float4* gC = (const float4*)&d_ag2[(nb + 2) * 64];
        const float4* gD = (const float4*)&d_ag2[(nb + 3) * 64];
        float4 aA = bb, aB = bb, aC = bb, aD = bb;
        #pragma unroll
        for (int kk = 0; kk < 16; kk++) {
            float4 w0 = *(const float4*)&Ws[(kk * 4 + 0) * 128 + q * 4];
            float4 w1 = *(const float4*)&Ws[(kk * 4 + 1) * 128 + q * 4];
            float4 w2 = *(const float4*)&Ws[(kk * 4 + 2) * 128 + q * 4];
            float4 w3 = *(const float4*)&Ws[(kk * 4 + 3) * 128 + q * 4];
            float4 v;
            v = gA[kk];
            aA.x += v.x*w0.x + v.y*w1.x + v.z*w2.x + v.w*w3.x;
            aA.y += v.x*w0.y + v.y*w1.y + v.z*w2.y + v.w*w3.y;
            aA.z += v.x*w0.z + v.y*w1.z + v.z*w2.z + v.w*w3.z;
            aA.w += v.x*w0.w + v.y*w1.w + v.z*w2.w + v.w*w3.w;
            v = gB[kk];
            aB.x += v.x*w0.x + v.y*w1.x + v.z*w2.x + v.w*w3.x;
            aB.y += v.x*w0.y + v.y*w1.y + v.z*w2.y + v.w*w3.y;
            aB.z += v.x*w0.z + v.y*w1.z + v.z*w2.z + v.w*w3.z;
            aB.w += v.x*w0.w + v.y*w1.w + v.z*w2.w + v.w*w3.w;
            v = gC[kk];
            aC.x += v.x*w0.x + v.y*w1.x + v.z*w2.x + v.w*w3.x;
            aC.y += v.x*w0.y + v.y*w1.y + v.z*w2.y + v.w*w3.y;
            aC.z += v.x*w0.z + v.y*w1.z + v.z*w2.z + v.w*w3.z;
            aC.w += v.x*w0.w + v.y*w1.w + v.z*w2.w + v.w*w3.w;
            v = gD[kk];
            aD.x += v.x*w0.x + v.y*w1.x + v.z*w2.x + v.w*w3.x;
            aD.y += v.x*w0.y + v.y*w1.y + v.z*w2.y + v.w*w3.y;
            aD.z += v.x*w0.z + v.y*w1.z + v.z*w2.z + v.w*w3.z;
            aD.w += v.x*w0.w + v.y*w1.w + v.z*w2.w + v.w*w3.w;
        }
        int b0 = batch[nb + 0], b1 = batch[nb + 1];
        int b2i = batch[nb + 2], b3i = batch[nb + 3];
        redAdd4(&d_pool[b0 * 128 + q * 4],
                lrelu(aA.x,0.01f), lrelu(aA.y,0.01f), lrelu(aA.z,0.01f), lrelu(aA.w,0.01f));
        redAdd4(&d_pool[b1 * 128 + q * 4],
                lrelu(aB.x,0.01f), lrelu(aB.y,0.01f), lrelu(aB.z,0.01f), lrelu(aB.w,0.01f));
        redAdd4(&d_pool[b2i * 128 + q * 4],
                lrelu(aC.x,0.01f), lrelu(aC.y,0.01f), lrelu(aC.z,0.01f), lrelu(aC.w,0.01f));
        redAdd4(&d_pool[b3i * 128 + q * 4],
                lrelu(aD.x,0.01f), lrelu(aD.y,0.01f), lrelu(aD.z,0.01f), lrelu(aD.w,0.01f));
    }
}

// ---------------- fusion + classifier head + state reset ----------------------
__global__ void k_head(const float* __restrict__ fusW, const float* __restrict__ fusb,
                       const float* __restrict__ c1W, const float* __restrict__ c1b,
                       const float* __restrict__ c3W, const float* __restrict__ c3b,
                       float* __restrict__ out) {
    __shared__ float comb[192], t1[128], t2[64];
    int b = blockIdx.x, tid = threadIdx.x;          // 128 threads
    if (tid < 128) comb[tid] = d_pool[b * 128 + tid] / fmaxf(d_cnt[b], 1.0f);
    if (tid < 64)  comb[128 + tid] = d_fc[b * 64 + tid];
    __syncthreads();
    // ---- reset persistent state for the next graph replay (post-read) ----
    d_pool[b * 128 + tid] = 0.f;
    if (tid == 0) d_cnt[b] = 0.f;
    if (b == 0 && tid == 0) d_scan_ctr = 0;
    {
        int gi = b * 128 + tid;                     // BB*128 = 131072 >= NN
        if (gi < NN) d_degi[gi] = 0;
    }
    // ----------------------------------------------------------------------
    float acc = fusb[tid];
    #pragma unroll 8
    for (int k = 0; k < 192; k++) acc += comb[k] * fusW[k * 128 + tid];
    t1[tid] = lrelu(acc, 0.01f);
    __syncthreads();
    if (tid < 64) {
        float a = c1b[tid];
        #pragma unroll 8
        for (int k = 0; k < 128; k++) a += t1[k] * c1W[k * 64 + tid];
        t2[tid] = lrelu(a, 0.01f);
    }
    __syncthreads();
    if (tid == 0) {
        float a = c3b[0];
        #pragma unroll 8
        for (int k = 0; k < 64; k++) a += t2[k] * c3W[k];
        out[b] = a;
    }
}

// ---------------- launch ------------------------------------------------------
extern "C" void kernel_launch(void* const* d_in, const int* in_sizes, int n_in,
                              void* d_out, int out_size) {
    const float* x     = (const float*)d_in[0];
    const int*   ei    = (const int*)  d_in[1];
    const int*   batch = (const int*)  d_in[2];
    const float* seq   = (const float*)d_in[3];
    const float* Wg    = (const float*)d_in[4];
    const float* atts  = (const float*)d_in[5];
    const float* attd  = (const float*)d_in[6];
    const float* bg    = (const float*)d_in[7];
    const float* W2    = (const float*)d_in[8];
    const float* b2    = (const float*)d_in[9];
    const float* W3    = (const float*)d_in[10];
    const float* b3    = (const float*)d_in[11];
    const float* c1w   = (const float*)d_in[12];
    const float* c1bv  = (const float*)d_in[13];
    const float* c2w   = (const float*)d_in[14];
    const float* c2bv  = (const float*)d_in[15];
    const float* bn1g  = (const float*)d_in[16];
    const float* bn1b  = (const float*)d_in[17];
    const float* bn1m  = (const float*)d_in[18];
    const float* bn1v  = (const float*)d_in[19];
    const float* bn2g  = (const float*)d_in[20];
    const float* bn2b  = (const float*)d_in[21];
    const float* bn2m  = (const float*)d_in[22];
    const float* bn2v  = (const float*)d_in[23];
    const float* fcW   = (const float*)d_in[24];
    const float* fcb   = (const float*)d_in[25];
    const float* fusW  = (const float*)d_in[26];
    const float* fusb  = (const float*)d_in[27];
    const float* cls1W = (const float*)d_in[28];
    const float* cls1b = (const float*)d_in[29];
    const float* cls3W = (const float*)d_in[30];
    const float* cls3b = (const float*)d_in[31];
    float* out = (float*)d_out;

    k_nodehist <<<(EE + 255) / 256, 256>>>(x, Wg, atts, attd, ei, batch);
    k_scan     <<<SCAN_B, 1024>>>();
    k_fill     <<<(EE + 255) / 256, 256>>>(ei);
    k_gat      <<<12500, 256>>>(Wg, bg);
    k_gemm1seq <<<GEMM1_BLOCKS + BB, 256>>>(W2, seq, c1w, c1bv, bn1g, bn1b, bn1m, bn1v,
                                            c2w, c2bv, bn2g, bn2b, bn2m, bn2v, fcW, fcb);
    k_gcn1     <<<12500, 256>>>(b2);
    k_gcn2agg  <<<12500, 256>>>();
    k_gemm2pool<<<3125, 256>>>(W3, b3, batch);
    k_head     <<<BB, 128>>>(fusW, fusb, cls1W, cls1b, cls3W, cls3b, out);
}